// round 5
// baseline (speedup 1.0000x reference)
#include <cuda_runtime.h>
#include <math.h>

#define NB 4
#define TDIM 8
#define LP1 197
#define HH 12
#define DD 64
#define CC 768
#define LL 196
#define NT 28   // NB*(TDIM-1)

typedef unsigned long long u64;

__device__ __forceinline__ u64 pk2(float lo, float hi) {
    u64 r; asm("mov.b64 %0,{%1,%2};" : "=l"(r) : "f"(lo), "f"(hi)); return r;
}
__device__ __forceinline__ void upk2(u64 v, float& lo, float& hi) {
    asm("mov.b64 {%0,%1},%2;" : "=f"(lo), "=f"(hi) : "l"(v));
}
__device__ __forceinline__ u64 ffma2(u64 a, u64 b, u64 c) {
    u64 d; asm("fma.rn.f32x2 %0,%1,%2,%3;" : "=l"(d) : "l"(a), "l"(b), "l"(c)); return d;
}
__device__ __forceinline__ u64 fadd2(u64 a, u64 b) {
    u64 d; asm("add.rn.f32x2 %0,%1,%2;" : "=l"(d) : "l"(a), "l"(b)); return d;
}
__device__ __forceinline__ void red2(float* p, float a, float b) {
    asm volatile("red.global.add.v2.f32 [%0], {%1,%2};" :: "l"(p), "f"(a), "f"(b) : "memory");
}

// Scratch: head-averaged attention probabilities for each half.
__device__ float g_P1[NT * LL * LL];
__device__ float g_P2[NT * LL * LL];

// ---------------------------------------------------------------------------
// Kernel 0: zero P scratch and the cls (q=0) rows of out.
// ---------------------------------------------------------------------------
__global__ void zero_kernel(float* __restrict__ out) {
    size_t stride = (size_t)gridDim.x * blockDim.x;
    size_t i = (size_t)blockIdx.x * blockDim.x + threadIdx.x;
    const size_t np = (size_t)NT * LL * LL;
    for (size_t j = i; j < np; j += stride) { g_P1[j] = 0.f; g_P2[j] = 0.f; }
    const size_t ncls = (size_t)NB * TDIM * CC;
    for (size_t j = i; j < ncls; j += stride) {
        size_t nt = j / CC, c = j - nt * CC;
        out[(nt * LP1) * CC + c] = 0.f;
    }
}

// ---------------------------------------------------------------------------
// Kernel 1: attention (unchanged from round 4 — protected win).
// ---------------------------------------------------------------------------
#define KS_STRIDE 210
#define QS_STRIDE 65
#define A_SMEM_BYTES ((64*KS_STRIDE + 64*QS_STRIDE) * 4)

__global__ __launch_bounds__(256, 3)
void attn_kernel(const float* __restrict__ q, const float* __restrict__ k) {
    extern __shared__ float sm[];
    float* ks = sm;                          // [64][210]
    float* qs = ks + 64 * KS_STRIDE;         // [64][65]

    int h    = blockIdx.x;
    int nt   = blockIdx.y;
    int half = blockIdx.z >> 1;
    int qh   = blockIdx.z & 1;
    int n = nt / 7, t = nt - n * 7;
    int tq = (half == 0) ? t + 1 : t;
    int tk = (half == 0) ? t : t + 1;

    const float* qb = q + ((size_t)(n * TDIM + tq) * LP1 + 1) * (HH * DD) + h * DD;
    const float* kb = k + ((size_t)(n * TDIM + tk) * LP1 + 1) * (HH * DD) + h * DD;
    float* P = ((half == 0) ? g_P1 : g_P2) + (size_t)nt * LL * LL;

    int tid = threadIdx.x;

    for (int i = tid; i < LL * DD; i += 256) {
        int kk = i >> 6, d = i & 63;
        ks[d * KS_STRIDE + kk] = kb[(size_t)kk * (HH * DD) + d];
    }

    int tx = tid & 15, ty = tid >> 4;

    for (int chunk = 0; chunk < 2; chunk++) {
        int q0 = qh * 98 + chunk * 49;
        __syncthreads();

        for (int i = tid; i < 49 * DD; i += 256) {
            int qq = i >> 6, d = i & 63;
            qs[d * QS_STRIDE + qq] = qb[(size_t)(q0 + qq) * (HH * DD) + d] * 0.125f;
        }
        __syncthreads();

        u64 acc[4][7];
        #pragma unroll
        for (int a = 0; a < 4; a++)
            #pragma unroll
            for (int b = 0; b < 7; b++) acc[a][b] = 0ULL;

        #pragma unroll 4
        for (int d = 0; d < 64; d++) {
            u64 ad[4], bv[7];
            #pragma unroll
            for (int a = 0; a < 4; a++) {
                float av = qs[d * QS_STRIDE + ty + 16 * a];
                ad[a] = pk2(av, av);
            }
            #pragma unroll
            for (int b = 0; b < 7; b++)
                bv[b] = *(const u64*)&ks[d * KS_STRIDE + 2 * tx + 32 * b];
            #pragma unroll
            for (int a = 0; a < 4; a++)
                #pragma unroll
                for (int b = 0; b < 7; b++)
                    acc[a][b] = ffma2(ad[a], bv[b], acc[a][b]);
        }

        #pragma unroll
        for (int a = 0; a < 4; a++) {
            int r = ty + 16 * a;
            float e[14];
            #pragma unroll
            for (int b = 0; b < 7; b++) upk2(acc[a][b], e[2 * b], e[2 * b + 1]);

            bool v6 = (tx < 2);
            float mx = -1e30f;
            #pragma unroll
            for (int b = 0; b < 6; b++) mx = fmaxf(mx, fmaxf(e[2 * b], e[2 * b + 1]));
            if (v6) mx = fmaxf(mx, fmaxf(e[12], e[13]));
            #pragma unroll
            for (int off = 8; off > 0; off >>= 1)
                mx = fmaxf(mx, __shfl_xor_sync(0xffffffffu, mx, off));

            float s = 0.f;
            #pragma unroll
            for (int b = 0; b < 6; b++) {
                e[2 * b]     = __expf(e[2 * b] - mx);
                e[2 * b + 1] = __expf(e[2 * b + 1] - mx);
                s += e[2 * b] + e[2 * b + 1];
            }
            if (v6) {
                e[12] = __expf(e[12] - mx);
                e[13] = __expf(e[13] - mx);
                s += e[12] + e[13];
            }
            #pragma unroll
            for (int off = 8; off > 0; off >>= 1)
                s += __shfl_xor_sync(0xffffffffu, s, off);

            float inv = (1.f / 12.f) / s;
            if (r < 49) {
                float* Pr = P + (size_t)(q0 + r) * LL + 2 * tx;
                #pragma unroll
                for (int b = 0; b < 6; b++)
                    red2(Pr + 32 * b, e[2 * b] * inv, e[2 * b + 1] * inv);
                if (v6) red2(Pr + 192, e[12] * inv, e[13] * inv);
            }
        }
    }
}

// ---------------------------------------------------------------------------
// Kernel 2 (fused halves): out[n,tt,q+1,c] = sum_k P1[n,tt-1,q,k]*w1[IDX[q,k],c]
//                                          + sum_k P2[n,tt  ,q,k]*w2[IDX[q,k],c]
// Block = (c-tile 64, q, n-pair).  256 threads, 3 CTAs/SM.
// NEW inner structure: lane = (sub, cl): cl = 4 consecutive columns (LDS.128),
// sub = k-parity (warp covers 2 k rows/iter).  P pairs loaded as 2x LDS.128 in
// f32x2 layout (no repack).  3 LDS.128 per 2 k-rows vs 10 LDS.64 before.
// ---------------------------------------------------------------------------
#define TCo 64
#define WS_FLOATS (98 * TCo)            // 6272
#define PS_FLOATS (2 * LL * 8)          // 3136 per half
#define O_SMEM_BYTES ((WS_FLOATS + 2 * PS_FLOATS) * 4)   // 50176 B

__global__ __launch_bounds__(256, 3)
void out_kernel(const float* __restrict__ w1, const float* __restrict__ w2,
                float* __restrict__ out) {
    extern __shared__ float sm[];
    float* ws  = sm;                    // [98][64]
    float* psA = sm + WS_FLOATS;        // [2][196*8]  slot tt = P1[t=tt-1], slot0=0
    float* psB = psA + PS_FLOATS;       // [2][196*8]  slot tt = P2[tt],    slot7=0

    int qq = blockIdx.y;
    int c0 = blockIdx.x * TCo;
    int np = blockIdx.z;
    int tid = threadIdx.x;
    int pi = qq / 14, pj = qq - pi * 14;

    // Stage P rows t-strided (both halves, both local n).
    #pragma unroll
    for (int r = 0; r < 14; r++) {
        int n_l = r / 7, t = r - n_l * 7;
        if (tid < LL) {
            int n = np * 2 + n_l;
            size_t base = ((size_t)(n * 7 + t) * LL + qq) * LL + tid;
            psA[n_l * (LL * 8) + tid * 8 + t + 1] = g_P1[base];
            psB[n_l * (LL * 8) + tid * 8 + t]     = g_P2[base];
        }
    }
    if (tid < LL) {
        psA[tid * 8] = 0.f;            psA[LL * 8 + tid * 8] = 0.f;
        psB[tid * 8 + 7] = 0.f;        psB[LL * 8 + tid * 8 + 7] = 0.f;
    }

    int wid = tid >> 5, lane = tid & 31;
    int n_l = wid >> 2, kq = wid & 3;
    int sub = lane >> 4, cl = lane & 15;
    // even-sized k slices of 98: 26,24,24,24
    int kst = (kq == 0) ? 0 : (26 + (kq - 1) * 24);
    int kcn = (kq == 0) ? 26 : 24;

    u64 acc[16];   // acc[c*4 + tp]: column cl*4+c, tt-pair (2tp, 2tp+1)
    #pragma unroll
    for (int i = 0; i < 16; i++) acc[i] = 0ULL;

    #pragma unroll
    for (int ph = 0; ph < 4; ph++) {
        const float* w = (ph < 2) ? w1 : w2;
        const float* ps = ((ph < 2) ? psA : psB) + n_l * (LL * 8);
        int kbase = (ph & 1) * 98;

        __syncthreads();   // ws free to overwrite (and ps staged, for ph=0)
        for (int i = tid; i < 98 * 16; i += 256) {
            int kk = i >> 4, cq = i & 15;
            int kg = kbase + kk;
            int ki = kg / 14, kj = kg - ki * 14;
            int idx = (pi - ki + 13) * 27 + (pj - kj + 13);
            *(float4*)&ws[kk * TCo + cq * 4] =
                *(const float4*)(w + (size_t)idx * CC + c0 + cq * 4);
        }
        __syncthreads();

        #pragma unroll 6
        for (int kl = kst; kl < kst + kcn; kl += 2) {
            int kk = kl + sub;                      // this thread's k row
            float4 wv = *(const float4*)&ws[kk * TCo + cl * 4];
            ulonglong2 pA = *(const ulonglong2*)&ps[(kbase + kk) * 8];      // (t0,t1)(t2,t3)
            ulonglong2 pB = *(const ulonglong2*)&ps[(kbase + kk) * 8 + 4];  // (t4,t5)(t6,t7)
            u64 b0 = pk2(wv.x, wv.x), b1 = pk2(wv.y, wv.y);
            u64 b2 = pk2(wv.z, wv.z), b3 = pk2(wv.w, wv.w);
            acc[0]  = ffma2(pA.x, b0, acc[0]);  acc[1]  = ffma2(pA.y, b0, acc[1]);
            acc[2]  = ffma2(pB.x, b0, acc[2]);  acc[3]  = ffma2(pB.y, b0, acc[3]);
            acc[4]  = ffma2(pA.x, b1, acc[4]);  acc[5]  = ffma2(pA.y, b1, acc[5]);
            acc[6]  = ffma2(pB.x, b1, acc[6]);  acc[7]  = ffma2(pB.y, b1, acc[7]);
            acc[8]  = ffma2(pA.x, b2, acc[8]);  acc[9]  = ffma2(pA.y, b2, acc[9]);
            acc[10] = ffma2(pB.x, b2, acc[10]); acc[11] = ffma2(pB.y, b2, acc[11]);
            acc[12] = ffma2(pA.x, b3, acc[12]); acc[13] = ffma2(pA.y, b3, acc[13]);
            acc[14] = ffma2(pB.x, b3, acc[14]); acc[15] = ffma2(pB.y, b3, acc[15]);
        }
    }

    // Reduce k-parity (sub) within the warp: 64-bit shfl over lane 16.
    #pragma unroll
    for (int i = 0; i < 16; i++)
        acc[i] = fadd2(acc[i], __shfl_xor_sync(0xffffffffu, acc[i], 16));

    // Cross-kq reduction through smem (reuse ws area).
    __syncthreads();   // everyone done reading ws
    u64* red = (u64*)ws;
    if (kq && sub == 0) {
        int base = ((n_l * 3 + (kq - 1)) * 16 + cl) * 16;
        #pragma unroll
        for (int j = 0; j < 16; j++) red[base + j] = acc[j];
    }
    __syncthreads();

    if (kq == 0 && sub == 0) {
        #pragma unroll
        for (int ww = 0; ww < 3; ww++) {
            int base = ((n_l * 3 + ww) * 16 + cl) * 16;
            #pragma unroll
            for (int j = 0; j < 16; j++) acc[j] = fadd2(acc[j], red[base + j]);
        }
        int n = np * 2 + n_l;
        float a[32];
        #pragma unroll
        for (int i = 0; i < 16; i++) upk2(acc[i], a[2 * i], a[2 * i + 1]);
        #pragma unroll
        for (int tt = 0; tt < 8; tt++) {
            int tp = tt >> 1, hi = tt & 1;
            float4 o4;
            o4.x = a[(0 * 4 + tp) * 2 + hi];
            o4.y = a[(1 * 4 + tp) * 2 + hi];
            o4.z = a[(2 * 4 + tp) * 2 + hi];
            o4.w = a[(3 * 4 + tp) * 2 + hi];
            *(float4*)(out + ((size_t)(n * TDIM + tt) * LP1 + qq + 1) * CC
                       + c0 + cl * 4) = o4;
        }
    }
}

// ---------------------------------------------------------------------------
extern "C" void kernel_launch(void* const* d_in, const int* in_sizes, int n_in,
                              void* d_out, int out_size) {
    const float* q  = (const float*)d_in[0];
    const float* k  = (const float*)d_in[1];
    const float* w1 = (const float*)d_in[2];
    const float* w2 = (const float*)d_in[3];
    float* out = (float*)d_out;

    cudaFuncSetAttribute(attn_kernel, cudaFuncAttributeMaxDynamicSharedMemorySize, A_SMEM_BYTES);
    cudaFuncSetAttribute(out_kernel,  cudaFuncAttributeMaxDynamicSharedMemorySize, O_SMEM_BYTES);

    zero_kernel<<<512, 256>>>(out);
    attn_kernel<<<dim3(HH, NT, 4), 256, A_SMEM_BYTES>>>(q, k);
    out_kernel<<<dim3(CC / TCo, LL, NB / 2), 256, O_SMEM_BYTES>>>(w1, w2, out);
}